// round 4
// baseline (speedup 1.0000x reference)
#include <cuda_runtime.h>
#include <cstdint>

#define N_NODES 100000
#define N_EDGES 1250000
#define D 64
#define NB 196  // ceil(N_NODES / 512) scan blocks

// ---- device scratch (no allocation allowed) ----
__device__ int g_cnt[N_NODES];       // histogram, then fill cursor
__device__ int g_off[N_NODES + 1];   // CSR offsets
__device__ int g_csr[N_EDGES];       // src node per CSR slot
__device__ int g_bsum[NB];           // scan block sums
__device__ int g_idx_is64;

// ---------------------------------------------------------------------------
// Kernel: zero counters, set g_off[N], detect edge_index dtype.
// int64 little-endian => every odd 32-bit word of values < 100000 is zero.
// ---------------------------------------------------------------------------
__global__ void init_kernel(const int* __restrict__ ei32) {
    int i = blockIdx.x * blockDim.x + threadIdx.x;
    if (i < N_NODES) g_cnt[i] = 0;
    if (blockIdx.x == 0 && threadIdx.x == 0) {
        g_off[N_NODES] = N_EDGES;
        int is64 = 1;
        #pragma unroll 1
        for (int k = 1; k < 128; k += 2) {
            if (ei32[k] != 0) { is64 = 0; break; }
        }
        g_idx_is64 = is64;
    }
}

// ---------------------------------------------------------------------------
// Kernel: histogram of dst.
// ---------------------------------------------------------------------------
__global__ void hist_kernel(const void* __restrict__ ei) {
    int e = blockIdx.x * blockDim.x + threadIdx.x;
    if (e >= N_EDGES) return;
    int d;
    if (g_idx_is64) d = (int)((const long long*)ei)[N_EDGES + e];
    else            d = ((const int*)ei)[N_EDGES + e];
    atomicAdd(&g_cnt[d], 1);
}

// ---------------------------------------------------------------------------
// Scan: block sums, then per-block (base-reduction + local scan) in one kernel.
// ---------------------------------------------------------------------------
__global__ __launch_bounds__(512) void scanA_kernel() {
    __shared__ int sm[512];
    int t = threadIdx.x;
    int i = blockIdx.x * 512 + t;
    sm[t] = (i < N_NODES) ? g_cnt[i] : 0;
    __syncthreads();
    #pragma unroll
    for (int s = 256; s > 0; s >>= 1) {
        if (t < s) sm[t] += sm[t + s];
        __syncthreads();
    }
    if (t == 0) g_bsum[blockIdx.x] = sm[0];
}

__global__ __launch_bounds__(512) void scanC_kernel() {
    __shared__ int sm[512];
    int t = threadIdx.x;
    int i = blockIdx.x * 512 + t;

    // base = sum of g_bsum[0 .. blockIdx.x)
    sm[t] = (t < blockIdx.x) ? g_bsum[t] : 0;  // NB=196 < 512
    __syncthreads();
    #pragma unroll
    for (int s = 256; s > 0; s >>= 1) {
        if (t < s) sm[t] += sm[t + s];
        __syncthreads();
    }
    int base = sm[0];
    __syncthreads();

    // local inclusive scan of this block's 512 counts
    int v = (i < N_NODES) ? g_cnt[i] : 0;
    sm[t] = v;
    __syncthreads();
    #pragma unroll
    for (int s = 1; s < 512; s <<= 1) {
        int a = (t >= s) ? sm[t - s] : 0;
        __syncthreads();
        sm[t] += a;
        __syncthreads();
    }
    if (i < N_NODES) {
        int excl = sm[t] - v + base;
        g_off[i] = excl;
        g_cnt[i] = excl;  // cursor for fill
    }
}

// ---------------------------------------------------------------------------
// Kernel: fill CSR slots. pos = cursor[dst]++, csr[pos] = src.
// ---------------------------------------------------------------------------
__global__ void fill_kernel(const void* __restrict__ ei) {
    int e = blockIdx.x * blockDim.x + threadIdx.x;
    if (e >= N_EDGES) return;
    int s, d;
    if (g_idx_is64) {
        const long long* p = (const long long*)ei;
        s = (int)p[e];
        d = (int)p[N_EDGES + e];
    } else {
        const int* p = (const int*)ei;
        s = p[e];
        d = p[N_EDGES + e];
    }
    int pos = atomicAdd(&g_cnt[d], 1);
    g_csr[pos] = s;
}

// ---------------------------------------------------------------------------
// Kernel: fused gather + MLP.
// Block = 256 threads, tile = 64 nodes.
// Phase 1: warp w gathers nodes w*8..w*8+7 (lane owns cols {l, l+32}) into hs.
// Phase 2: register-tiled MLP (tx 0..15, ty 0..15; 4x4 tile per thread).
// ---------------------------------------------------------------------------
#define HS_STRIDE 68  // 64 + 4 pad; multiple of 4 keeps float4 alignment

__global__ __launch_bounds__(256) void gmlp_kernel(
    const float* __restrict__ x,
    const float* __restrict__ W1, const float* __restrict__ b1,
    const float* __restrict__ W2, const float* __restrict__ b2,
    float* __restrict__ out)
{
    __shared__ float W1s[D * D];
    __shared__ float W2s[D * D];
    __shared__ float hs[64][HS_STRIDE];

    const int tid = threadIdx.x;
    const int node_base = blockIdx.x * 64;

    // Stage weights (covered by the barrier after gather).
    #pragma unroll
    for (int i = tid; i < D * D; i += 256) {
        W1s[i] = W1[i];
        W2s[i] = W2[i];
    }

    // ---- Phase 1: gather h = x[n] + sum_{src in N(n)} x[src] ----
    {
        const int warp = tid >> 5;
        const int lane = tid & 31;
        #pragma unroll 1
        for (int i = 0; i < 8; i++) {
            int nd = warp * 8 + i;
            int g = node_base + nd;
            float a0 = 0.f, a1 = 0.f;
            if (g < N_NODES) {
                a0 = x[(size_t)g * D + lane];
                a1 = x[(size_t)g * D + lane + 32];
                int beg = g_off[g];
                int end = g_off[g + 1];
                int j = beg;
                for (; j + 1 < end; j += 2) {
                    int s0 = g_csr[j];
                    int s1 = g_csr[j + 1];
                    float v00 = x[(size_t)s0 * D + lane];
                    float v01 = x[(size_t)s0 * D + lane + 32];
                    float v10 = x[(size_t)s1 * D + lane];
                    float v11 = x[(size_t)s1 * D + lane + 32];
                    a0 += v00; a1 += v01;
                    a0 += v10; a1 += v11;
                }
                if (j < end) {
                    int s0 = g_csr[j];
                    a0 += x[(size_t)s0 * D + lane];
                    a1 += x[(size_t)s0 * D + lane + 32];
                }
            }
            hs[nd][lane]      = a0;
            hs[nd][lane + 32] = a1;
        }
    }
    __syncthreads();

    // ---- Phase 2: MLP ----
    const int tx = tid & 15;
    const int ty = tid >> 4;
    float acc[4][4];

    // Layer 1: t = relu(h @ W1 + b1)
    {
        float4 bv = reinterpret_cast<const float4*>(b1)[tx];
        #pragma unroll
        for (int r = 0; r < 4; r++) {
            acc[r][0] = bv.x; acc[r][1] = bv.y; acc[r][2] = bv.z; acc[r][3] = bv.w;
        }
    }
    #pragma unroll 4
    for (int k0 = 0; k0 < D; k0 += 4) {
        float hr[4][4];
        #pragma unroll
        for (int r = 0; r < 4; r++) {
            *reinterpret_cast<float4*>(hr[r]) =
                *reinterpret_cast<const float4*>(&hs[ty * 4 + r][k0]);
        }
        #pragma unroll
        for (int kk = 0; kk < 4; kk++) {
            float4 w = *reinterpret_cast<const float4*>(&W1s[(k0 + kk) * D + tx * 4]);
            #pragma unroll
            for (int r = 0; r < 4; r++) {
                acc[r][0] += hr[r][kk] * w.x;
                acc[r][1] += hr[r][kk] * w.y;
                acc[r][2] += hr[r][kk] * w.z;
                acc[r][3] += hr[r][kk] * w.w;
            }
        }
    }
    __syncthreads();

    // ReLU, write t back into hs.
    #pragma unroll
    for (int r = 0; r < 4; r++) {
        float4 t;
        t.x = fmaxf(acc[r][0], 0.f);
        t.y = fmaxf(acc[r][1], 0.f);
        t.z = fmaxf(acc[r][2], 0.f);
        t.w = fmaxf(acc[r][3], 0.f);
        *reinterpret_cast<float4*>(&hs[ty * 4 + r][tx * 4]) = t;
    }
    __syncthreads();

    // Layer 2: out = t @ W2 + b2
    {
        float4 bv = reinterpret_cast<const float4*>(b2)[tx];
        #pragma unroll
        for (int r = 0; r < 4; r++) {
            acc[r][0] = bv.x; acc[r][1] = bv.y; acc[r][2] = bv.z; acc[r][3] = bv.w;
        }
    }
    #pragma unroll 4
    for (int k0 = 0; k0 < D; k0 += 4) {
        float hr[4][4];
        #pragma unroll
        for (int r = 0; r < 4; r++) {
            *reinterpret_cast<float4*>(hr[r]) =
                *reinterpret_cast<const float4*>(&hs[ty * 4 + r][k0]);
        }
        #pragma unroll
        for (int kk = 0; kk < 4; kk++) {
            float4 w = *reinterpret_cast<const float4*>(&W2s[(k0 + kk) * D + tx * 4]);
            #pragma unroll
            for (int r = 0; r < 4; r++) {
                acc[r][0] += hr[r][kk] * w.x;
                acc[r][1] += hr[r][kk] * w.y;
                acc[r][2] += hr[r][kk] * w.z;
                acc[r][3] += hr[r][kk] * w.w;
            }
        }
    }

    #pragma unroll
    for (int r = 0; r < 4; r++) {
        int g = node_base + ty * 4 + r;
        if (g < N_NODES) {
            float4 o = make_float4(acc[r][0], acc[r][1], acc[r][2], acc[r][3]);
            reinterpret_cast<float4*>(out)[(size_t)g * 16 + tx] = o;
        }
    }
}

// ---------------------------------------------------------------------------
// Launch. Inputs (metadata order): x, edge_index, W1, b1, W2, b2
// ---------------------------------------------------------------------------
extern "C" void kernel_launch(void* const* d_in, const int* in_sizes, int n_in,
                              void* d_out, int out_size) {
    const float* x  = (const float*)d_in[0];
    const void*  ei = d_in[1];
    const float* W1 = (const float*)d_in[2];
    const float* b1 = (const float*)d_in[3];
    const float* W2 = (const float*)d_in[4];
    const float* b2 = (const float*)d_in[5];
    float* out = (float*)d_out;

    init_kernel<<<(N_NODES + 255) / 256, 256>>>((const int*)ei);

    int eblocks = (N_EDGES + 255) / 256;
    hist_kernel<<<eblocks, 256>>>(ei);

    scanA_kernel<<<NB, 512>>>();
    scanC_kernel<<<NB, 512>>>();

    fill_kernel<<<eblocks, 256>>>(ei);

    gmlp_kernel<<<(N_NODES + 63) / 64, 256>>>(x, W1, b1, W2, b2, out);
}

// round 5
// speedup vs baseline: 1.0843x; 1.0843x over previous
#include <cuda_runtime.h>
#include <cstdint>

#define N_NODES 100000
#define N_EDGES 1250000
#define D 64
#define NB 196  // ceil(N_NODES / 512) scan blocks

typedef unsigned long long ull;

// ---- device scratch (no allocation allowed) ----
__device__ int g_cnt[N_NODES];       // histogram, then fill cursor
__device__ int g_off[N_NODES + 1];   // CSR offsets
__device__ int g_csr[N_EDGES];       // src node per CSR slot
__device__ int g_bsum[NB];           // scan block sums
__device__ int g_idx_is64;

// ---- f32x2 helpers ----
__device__ __forceinline__ ull pk2(float lo, float hi) {
    ull r;
    asm("mov.b64 %0, {%1, %2};" : "=l"(r) : "f"(lo), "f"(hi));
    return r;
}
__device__ __forceinline__ void upk2(float& lo, float& hi, ull v) {
    asm("mov.b64 {%0, %1}, %2;" : "=f"(lo), "=f"(hi) : "l"(v));
}
#define FMA2(acc, a, b) \
    asm("fma.rn.f32x2 %0, %1, %2, %3;" : "=l"(acc) : "l"(a), "l"(b), "l"(acc))

// ---------------------------------------------------------------------------
// Kernel: zero counters, set g_off[N], detect edge_index dtype.
// int64 little-endian => every odd 32-bit word of values < 100000 is zero.
// ---------------------------------------------------------------------------
__global__ void init_kernel(const int* __restrict__ ei32) {
    int i = blockIdx.x * blockDim.x + threadIdx.x;
    if (i < N_NODES) g_cnt[i] = 0;
    if (blockIdx.x == 0 && threadIdx.x == 0) {
        g_off[N_NODES] = N_EDGES;
        int is64 = 1;
        #pragma unroll 1
        for (int k = 1; k < 128; k += 2) {
            if (ei32[k] != 0) { is64 = 0; break; }
        }
        g_idx_is64 = is64;
    }
}

// ---------------------------------------------------------------------------
// Kernel: histogram of dst.
// ---------------------------------------------------------------------------
__global__ __launch_bounds__(512) void hist_kernel(const void* __restrict__ ei) {
    int e = blockIdx.x * blockDim.x + threadIdx.x;
    if (e >= N_EDGES) return;
    int d;
    if (g_idx_is64) d = (int)__ldg(&((const long long*)ei)[N_EDGES + e]);
    else            d = __ldg(&((const int*)ei)[N_EDGES + e]);
    atomicAdd(&g_cnt[d], 1);
}

// ---------------------------------------------------------------------------
// Scan A: per-512-block sums (warp shuffles).
// ---------------------------------------------------------------------------
__global__ __launch_bounds__(512) void scanA_kernel() {
    __shared__ int wsum[16];
    int t = threadIdx.x;
    int i = blockIdx.x * 512 + t;
    int v = (i < N_NODES) ? g_cnt[i] : 0;
    #pragma unroll
    for (int o = 16; o; o >>= 1) v += __shfl_down_sync(0xffffffffu, v, o);
    if ((t & 31) == 0) wsum[t >> 5] = v;
    __syncthreads();
    if (t < 16) {
        int s = wsum[t];
        #pragma unroll
        for (int o = 8; o; o >>= 1) s += __shfl_down_sync(0xffffu, s, o);
        if (t == 0) g_bsum[blockIdx.x] = s;
    }
}

// ---------------------------------------------------------------------------
// Scan C: base = sum(g_bsum[0..bid)) + local exclusive scan, shuffle-based.
// ---------------------------------------------------------------------------
__global__ __launch_bounds__(512) void scanC_kernel() {
    __shared__ int wsum[16];
    __shared__ int woff[16];
    __shared__ int sbase;
    int t = threadIdx.x, bid = blockIdx.x;
    int lane = t & 31, wid = t >> 5;
    int i = bid * 512 + t;

    // base reduction (bid <= 195 < 512)
    int bv = (t < bid) ? g_bsum[t] : 0;
    #pragma unroll
    for (int o = 16; o; o >>= 1) bv += __shfl_down_sync(0xffffffffu, bv, o);
    if (lane == 0) wsum[wid] = bv;
    __syncthreads();
    if (t < 16) {
        int s = wsum[t];
        #pragma unroll
        for (int o = 8; o; o >>= 1) s += __shfl_down_sync(0xffffu, s, o);
        if (t == 0) sbase = s;
    }
    __syncthreads();

    // local inclusive scan
    int v = (i < N_NODES) ? g_cnt[i] : 0;
    int xi = v;
    #pragma unroll
    for (int o = 1; o < 32; o <<= 1) {
        int y = __shfl_up_sync(0xffffffffu, xi, o);
        if (lane >= o) xi += y;
    }
    if (lane == 31) wsum[wid] = xi;
    __syncthreads();
    if (t < 16) {
        int s = wsum[t];
        int si = s;
        #pragma unroll
        for (int o = 1; o < 16; o <<= 1) {
            int y = __shfl_up_sync(0xffffu, si, o);
            if (t >= o) si += y;
        }
        woff[t] = si - s;  // exclusive warp offset
    }
    __syncthreads();
    if (i < N_NODES) {
        int excl = xi - v + woff[wid] + sbase;
        g_off[i] = excl;
        g_cnt[i] = excl;  // cursor for fill
    }
}

// ---------------------------------------------------------------------------
// Kernel: fill CSR slots. pos = cursor[dst]++, csr[pos] = src.
// ---------------------------------------------------------------------------
__global__ __launch_bounds__(512) void fill_kernel(const void* __restrict__ ei) {
    int e = blockIdx.x * blockDim.x + threadIdx.x;
    if (e >= N_EDGES) return;
    int s, d;
    if (g_idx_is64) {
        const long long* p = (const long long*)ei;
        s = (int)__ldg(&p[e]);
        d = (int)__ldg(&p[N_EDGES + e]);
    } else {
        const int* p = (const int*)ei;
        s = __ldg(&p[e]);
        d = __ldg(&p[N_EDGES + e]);
    }
    int pos = atomicAdd(&g_cnt[d], 1);
    g_csr[pos] = s;
}

// ---------------------------------------------------------------------------
// Kernel: fused gather + MLP.
// Block = 256 threads, tile = 64 nodes.
// Gather: half-warp per node, lane owns one float4 chunk, neighbor loop
//         unrolled by 4 (4 independent LDG.128 in flight).
// MLP:    register-tiled 4x4 per thread, math in packed f32x2 FFMA2.
// ---------------------------------------------------------------------------
#define HS_STRIDE 68  // 64 + 4 pad; multiple of 4 keeps float4 alignment

__global__ __launch_bounds__(256) void gmlp_kernel(
    const float* __restrict__ x,
    const float* __restrict__ W1, const float* __restrict__ b1,
    const float* __restrict__ W2, const float* __restrict__ b2,
    float* __restrict__ out)
{
    __shared__ float W1s[D * D];
    __shared__ float W2s[D * D];
    __shared__ float hs[64][HS_STRIDE];

    const int tid = threadIdx.x;
    const int node_base = blockIdx.x * 64;
    const float4* __restrict__ x4 = (const float4*)x;

    // Stage weights (float4), covered by the barrier after gather.
    #pragma unroll
    for (int i = tid; i < D * D / 4; i += 256) {
        reinterpret_cast<float4*>(W1s)[i] = reinterpret_cast<const float4*>(W1)[i];
        reinterpret_cast<float4*>(W2s)[i] = reinterpret_cast<const float4*>(W2)[i];
    }

    // ---- Phase 1: gather h = x[n] + sum_{src in N(n)} x[src] ----
    {
        const int hw = tid >> 4;   // half-warp id, 0..15 -> 4 nodes each
        const int hl = tid & 15;   // float4 chunk within row
        #pragma unroll 1
        for (int i = 0; i < 4; i++) {
            int nd = hw * 4 + i;
            int g = node_base + nd;
            float4 a = make_float4(0.f, 0.f, 0.f, 0.f);
            if (g < N_NODES) {
                a = x4[(size_t)g * 16 + hl];
                int beg = g_off[g];
                int end = g_off[g + 1];
                int j = beg;
                for (; j + 3 < end; j += 4) {
                    int s0 = g_csr[j];
                    int s1 = g_csr[j + 1];
                    int s2 = g_csr[j + 2];
                    int s3 = g_csr[j + 3];
                    float4 v0 = x4[(size_t)s0 * 16 + hl];
                    float4 v1 = x4[(size_t)s1 * 16 + hl];
                    float4 v2 = x4[(size_t)s2 * 16 + hl];
                    float4 v3 = x4[(size_t)s3 * 16 + hl];
                    a.x += v0.x + v1.x + v2.x + v3.x;
                    a.y += v0.y + v1.y + v2.y + v3.y;
                    a.z += v0.z + v1.z + v2.z + v3.z;
                    a.w += v0.w + v1.w + v2.w + v3.w;
                }
                for (; j < end; j++) {
                    int s0 = g_csr[j];
                    float4 v0 = x4[(size_t)s0 * 16 + hl];
                    a.x += v0.x; a.y += v0.y; a.z += v0.z; a.w += v0.w;
                }
            }
            *reinterpret_cast<float4*>(&hs[nd][hl * 4]) = a;
        }
    }
    __syncthreads();

    // ---- Phase 2: MLP (f32x2 packed) ----
    const int tx = tid & 15;
    const int ty = tid >> 4;
    ull a01[4], a23[4];

    // Layer 1: t = relu(h @ W1 + b1)
    {
        float4 bv = reinterpret_cast<const float4*>(b1)[tx];
        ull b01 = pk2(bv.x, bv.y), b23 = pk2(bv.z, bv.w);
        #pragma unroll
        for (int r = 0; r < 4; r++) { a01[r] = b01; a23[r] = b23; }
    }
    #pragma unroll 4
    for (int k0 = 0; k0 < D; k0 += 4) {
        float hr[4][4];
        #pragma unroll
        for (int r = 0; r < 4; r++) {
            *reinterpret_cast<float4*>(hr[r]) =
                *reinterpret_cast<const float4*>(&hs[ty * 4 + r][k0]);
        }
        #pragma unroll
        for (int kk = 0; kk < 4; kk++) {
            float4 w = *reinterpret_cast<const float4*>(&W1s[(k0 + kk) * D + tx * 4]);
            ull w01 = pk2(w.x, w.y), w23 = pk2(w.z, w.w);
            #pragma unroll
            for (int r = 0; r < 4; r++) {
                ull hh = pk2(hr[r][kk], hr[r][kk]);
                FMA2(a01[r], hh, w01);
                FMA2(a23[r], hh, w23);
            }
        }
    }
    __syncthreads();

    // ReLU, write t back into hs.
    #pragma unroll
    for (int r = 0; r < 4; r++) {
        float t0, t1, t2, t3;
        upk2(t0, t1, a01[r]);
        upk2(t2, t3, a23[r]);
        float4 t = make_float4(fmaxf(t0, 0.f), fmaxf(t1, 0.f),
                               fmaxf(t2, 0.f), fmaxf(t3, 0.f));
        *reinterpret_cast<float4*>(&hs[ty * 4 + r][tx * 4]) = t;
    }
    __syncthreads();

    // Layer 2: out = t @ W2 + b2
    {
        float4 bv = reinterpret_cast<const float4*>(b2)[tx];
        ull b01 = pk2(bv.x, bv.y), b23 = pk2(bv.z, bv.w);
        #pragma unroll
        for (int r = 0; r < 4; r++) { a01[r] = b01; a23[r] = b23; }
    }
    #pragma unroll 4
    for (int k0 = 0; k0 < D; k0 += 4) {
        float hr[4][4];
        #pragma unroll
        for (int r = 0; r < 4; r++) {
            *reinterpret_cast<float4*>(hr[r]) =
                *reinterpret_cast<const float4*>(&hs[ty * 4 + r][k0]);
        }
        #pragma unroll
        for (int kk = 0; kk < 4; kk++) {
            float4 w = *reinterpret_cast<const float4*>(&W2s[(k0 + kk) * D + tx * 4]);
            ull w01 = pk2(w.x, w.y), w23 = pk2(w.z, w.w);
            #pragma unroll
            for (int r = 0; r < 4; r++) {
                ull hh = pk2(hr[r][kk], hr[r][kk]);
                FMA2(a01[r], hh, w01);
                FMA2(a23[r], hh, w23);
            }
        }
    }

    #pragma unroll
    for (int r = 0; r < 4; r++) {
        int g = node_base + ty * 4 + r;
        if (g < N_NODES) {
            float o0, o1, o2, o3;
            upk2(o0, o1, a01[r]);
            upk2(o2, o3, a23[r]);
            reinterpret_cast<float4*>(out)[(size_t)g * 16 + tx] =
                make_float4(o0, o1, o2, o3);
        }
    }
}

// ---------------------------------------------------------------------------
// Launch. Inputs (metadata order): x, edge_index, W1, b1, W2, b2
// ---------------------------------------------------------------------------
extern "C" void kernel_launch(void* const* d_in, const int* in_sizes, int n_in,
                              void* d_out, int out_size) {
    const float* x  = (const float*)d_in[0];
    const void*  ei = d_in[1];
    const float* W1 = (const float*)d_in[2];
    const float* b1 = (const float*)d_in[3];
    const float* W2 = (const float*)d_in[4];
    const float* b2 = (const float*)d_in[5];
    float* out = (float*)d_out;

    init_kernel<<<(N_NODES + 255) / 256, 256>>>((const int*)ei);

    int eblocks = (N_EDGES + 511) / 512;
    hist_kernel<<<eblocks, 512>>>(ei);

    scanA_kernel<<<NB, 512>>>();
    scanC_kernel<<<NB, 512>>>();

    fill_kernel<<<eblocks, 512>>>(ei);

    gmlp_kernel<<<(N_NODES + 63) / 64, 256>>>(x, W1, b1, W2, b2, out);
}